// round 16
// baseline (speedup 1.0000x reference)
#include <cuda_runtime.h>
#include <cuda_bf16.h>
#include <cstdint>

// ---------------------------------------------------------------------------
// Constants fixed by the dataset:
//   N=1024 queries, B=4, D=384, NH=8, HD=48, HALF=24, NF=8, L=4, NS=7
//   total cells per batch = 5440, K(keys/query) = 196, Mkv = 21760
// ---------------------------------------------------------------------------
#define Dm 384
#define NHm 8
#define HDm 48
#define HALFm 24
#define Lm 4
#define NKEY 196
#define MAXQ 1024
#define MAXROWS 21760
#define KVW 768             // kvr row width (K 0..383 rotated, V 384..767)
#define KSPLIT 4            // out-GEMM split-K factor

// ---------------- device scratch (static; no cudaMalloc) -------------------
__device__ float g_qr[MAXQ * Dm];        // rotated+scaled q (fp32)
__device__ float g_attn[MAXQ * Dm];      // attention output
__device__ float g_part[KSPLIT * MAXQ * Dm];  // out-GEMM split-K partials
__device__ __align__(16) __nv_bfloat16 g_kvr[(size_t)MAXROWS * KVW];
__device__ float2 g_tab_s[128 * 8];      // cos/sin(pos * 10^(-f/8)), pos<128
__device__ float2 g_tab_l[4 * 8];        // cos/sin(lvl * 10^(+f/8))

// ---------------------------------------------------------------------------
__device__ __forceinline__ uint32_t pack_bf16x2(float lo, float hi) {
    uint32_t r;
    asm("cvt.rn.bf16x2.f32 %0, %1, %2;" : "=r"(r) : "f"(hi), "f"(lo));
    return r;
}

// ---------------------------------------------------------------------------
// RoPE cos/sin tables (tiny, once per launch)
// ---------------------------------------------------------------------------
__global__ void tab_kernel(float2* __restrict__ tab_s, float2* __restrict__ tab_l) {
    int t = blockIdx.x * blockDim.x + threadIdx.x;
    if (t < 128 * 8) {
        int p = t >> 3, f = t & 7;
        float s, c;
        sincosf((float)p * exp10f(-(float)f * 0.125f), &s, &c);
        tab_s[t] = make_float2(c, s);
    } else if (t < 128 * 8 + 32) {
        int u = t - 1024;
        int l = u >> 3, f = u & 7;
        float s, c;
        sincosf((float)l * exp10f((float)f * 0.125f), &s, &c);
        tab_l[u] = make_float2(c, s);
    }
}

// ---------------------------------------------------------------------------
// smem staging store: fp32 float4 -> interleaved bf16 pair layout
// ---------------------------------------------------------------------------
__device__ __forceinline__ void store_tile_u2(uint2* sm, int row, int c4, float4 v) {
    uint32_t lo = pack_bf16x2(v.x, v.y);
    uint32_t hi = pack_bf16x2(v.z, v.w);
    int P  = c4 >> 1;                 // even pair index in [0,16)
    int ks = P >> 3;
    int p0 = P & 7, p1 = (P + 1) & 7; // same ks (P even)
    uint32_t* base = (uint32_t*)(sm + row * 12 + ks * 4);
    base[((p0 & 3) << 1) | (p0 >> 2)] = lo;
    base[((p1 & 3) << 1) | (p1 >> 2)] = hi;
}

// ---------------------------------------------------------------------------
// Fused GEMM launch: kv projection (mode 1) + LN+q projection (mode 2).
// Blocks with by < kvTiles do kv tile (A=fm, W=wkv, N=768);
// blocks with by >= kvTiles and bx < 4 do q tile with LAYERNORM FUSED into
// the A staging (A=raw query, per-row mean/rstd computed in prologue).
// CTA tile 128x96, K=384, K-step 32, 8 warps 4(m)x2(n), double-buffered.
// ---------------------------------------------------------------------------
__global__ void __launch_bounds__(256)
gemm_fused_kernel(const float* __restrict__ fm, const float* __restrict__ wkv,
                  const float* __restrict__ query, const float* __restrict__ wq,
                  const float* __restrict__ nw, const float* __restrict__ nb,
                  float* __restrict__ qr, __nv_bfloat16* __restrict__ kvr,
                  const int* __restrict__ shapes, const int* __restrict__ pos,
                  const float2* __restrict__ tab_s, const float2* __restrict__ tab_l,
                  int Mkv, int NQ, int total, int kvTiles) {
    __shared__ uint2 As[2][128 * 12];
    __shared__ uint2 Bs[2][96 * 12];
    __shared__ int sh_Ws[Lm], sh_off[Lm];
    __shared__ float mu_s[128], rs_s[128];
    __shared__ float wgt[Dm], bias[Dm];

    const int tid  = threadIdx.x;
    const int lane = tid & 31;
    const int warp = tid >> 5;
    const int wm   = warp >> 1;   // 0..3
    const int wn   = warp & 1;    // 0..1
    const int tig  = lane & 3;
    const int gid  = lane >> 2;

    // ---- block role selection ----
    int mode, bm, bn, M;
    const float *A, *W;
    if ((int)blockIdx.y < kvTiles) {
        mode = 1;
        bm = blockIdx.y * 128;
        bn = blockIdx.x * 96;
        A = fm; W = wkv; M = Mkv;
    } else {
        if (blockIdx.x >= 4) return;
        mode = 2;
        bm = (blockIdx.y - kvTiles) * 128;
        bn = blockIdx.x * 96;
        A = query; W = wq; M = NQ;
    }
    const int K = Dm;

    if (mode == 1 && tid == 0) {
        int off = 0;
        #pragma unroll
        for (int l = 0; l < Lm; l++) {
            int H = shapes[2 * l], Wl = shapes[2 * l + 1];
            sh_Ws[l] = Wl; sh_off[l] = off; off += H * Wl;
        }
    }

    // ---- mode 2: LayerNorm stats for this tile's 128 rows ----
    if (mode == 2) {
        for (int i = tid; i < Dm; i += 256) { wgt[i] = nw[i]; bias[i] = nb[i]; }
        int r = tid >> 1, p = tid & 1;
        int gr = bm + r;
        float s = 0.f, s2 = 0.f;
        if (gr < M) {
            const float4* rp = (const float4*)(A + (size_t)gr * Dm + p * 192);
            #pragma unroll
            for (int i = 0; i < 48; i++) {
                float4 v = rp[i];
                s  += v.x + v.y + v.z + v.w;
                s2 += v.x * v.x + v.y * v.y + v.z * v.z + v.w * v.w;
            }
        }
        s  += __shfl_xor_sync(0xFFFFFFFFu, s,  1);
        s2 += __shfl_xor_sync(0xFFFFFFFFu, s2, 1);
        if (p == 0) {
            float mu  = s * (1.f / Dm);
            float var = s2 * (1.f / Dm) - mu * mu;
            mu_s[r] = mu;
            rs_s[r] = rsqrtf(var + 1e-5f);
        }
        __syncthreads();
    }

    float d[2][6][4];
    #pragma unroll
    for (int mt = 0; mt < 2; mt++)
        #pragma unroll
        for (int nt = 0; nt < 6; nt++)
            #pragma unroll
            for (int i = 0; i < 4; i++) d[mt][nt][i] = 0.f;

    const int nchunk = K >> 5;
    float4 pa[4], pb[3];

    // transform for mode 2: LayerNorm applied during staging
    auto xform = [&](float4 v, int row, int col) -> float4 {
        float mu = mu_s[row], rs = rs_s[row];
        v.x = (v.x - mu) * rs * wgt[col + 0] + bias[col + 0];
        v.y = (v.y - mu) * rs * wgt[col + 1] + bias[col + 1];
        v.z = (v.z - mu) * rs * wgt[col + 2] + bias[col + 2];
        v.w = (v.w - mu) * rs * wgt[col + 3] + bias[col + 3];
        return v;
    };

    #pragma unroll
    for (int i = 0; i < 4; i++) {
        int idx = tid + 256 * i;
        int row = idx >> 3, c4 = (idx & 7) << 2;
        int gr = bm + row;
        pa[i] = make_float4(0.f, 0.f, 0.f, 0.f);
        if (gr < M) {
            pa[i] = *(const float4*)(A + (size_t)gr * K + c4);
            if (mode == 2) pa[i] = xform(pa[i], row, c4);
        }
    }
    #pragma unroll
    for (int i = 0; i < 3; i++) {
        int idx = tid + 256 * i;
        int row = idx >> 3, c4 = (idx & 7) << 2;
        pb[i] = *(const float4*)(W + (size_t)(bn + row) * K + c4);
    }
    #pragma unroll
    for (int i = 0; i < 4; i++) {
        int idx = tid + 256 * i;
        store_tile_u2(As[0], idx >> 3, (idx & 7) << 2, pa[i]);
    }
    #pragma unroll
    for (int i = 0; i < 3; i++) {
        int idx = tid + 256 * i;
        store_tile_u2(Bs[0], idx >> 3, (idx & 7) << 2, pb[i]);
    }
    __syncthreads();

    for (int c = 0; c < nchunk; c++) {
        const int cur = c & 1;
        const bool more = (c + 1 < nchunk);

        if (more) {
            int k0 = (c + 1) * 32;
            #pragma unroll
            for (int i = 0; i < 4; i++) {
                int idx = tid + 256 * i;
                int row = idx >> 3, c4 = (idx & 7) << 2;
                int gr = bm + row;
                pa[i] = make_float4(0.f, 0.f, 0.f, 0.f);
                if (gr < M) {
                    pa[i] = *(const float4*)(A + (size_t)gr * K + k0 + c4);
                    if (mode == 2) pa[i] = xform(pa[i], row, k0 + c4);
                }
            }
            #pragma unroll
            for (int i = 0; i < 3; i++) {
                int idx = tid + 256 * i;
                int row = idx >> 3, c4 = (idx & 7) << 2;
                pb[i] = *(const float4*)(W + (size_t)(bn + row) * K + k0 + c4);
            }
        }

        #pragma unroll
        for (int ks = 0; ks < 2; ks++) {
            uint2 ua[2][2];
            #pragma unroll
            for (int mt = 0; mt < 2; mt++) {
                int r = wm * 32 + mt * 16 + gid;
                ua[mt][0] = As[cur][r * 12 + ks * 4 + tig];
                ua[mt][1] = As[cur][(r + 8) * 12 + ks * 4 + tig];
            }
            uint2 ub[6];
            #pragma unroll
            for (int nt = 0; nt < 6; nt++) {
                int nn = wn * 48 + nt * 8 + gid;
                ub[nt] = Bs[cur][nn * 12 + ks * 4 + tig];
            }
            #pragma unroll
            for (int mt = 0; mt < 2; mt++)
                #pragma unroll
                for (int nt = 0; nt < 6; nt++)
                    asm volatile(
                        "mma.sync.aligned.m16n8k16.row.col.f32.bf16.bf16.f32 "
                        "{%0,%1,%2,%3}, {%4,%5,%6,%7}, {%8,%9}, {%0,%1,%2,%3};"
                        : "+f"(d[mt][nt][0]), "+f"(d[mt][nt][1]),
                          "+f"(d[mt][nt][2]), "+f"(d[mt][nt][3])
                        : "r"(ua[mt][0].x), "r"(ua[mt][1].x),
                          "r"(ua[mt][0].y), "r"(ua[mt][1].y),
                          "r"(ub[nt].x), "r"(ub[nt].y));
        }

        if (more) {
            #pragma unroll
            for (int i = 0; i < 4; i++) {
                int idx = tid + 256 * i;
                store_tile_u2(As[cur ^ 1], idx >> 3, (idx & 7) << 2, pa[i]);
            }
            #pragma unroll
            for (int i = 0; i < 3; i++) {
                int idx = tid + 256 * i;
                store_tile_u2(Bs[cur ^ 1], idx >> 3, (idx & 7) << 2, pb[i]);
            }
        }
        __syncthreads();
    }

    if (mode == 2) {
        // q epilogue: rotate (nt, nt+3) pairs per query row, scale, fp32 out
        const int h = bn / HDm + wn;
        const float scale = 0.14433756729740643f;   // 1/sqrt(48)
        #pragma unroll
        for (int mt = 0; mt < 2; mt++) {
            #pragma unroll
            for (int rh = 0; rh < 2; rh++) {
                int row = bm + wm * 32 + mt * 16 + gid + rh * 8;
                if (row >= M) continue;
                int qi = pos[row * 4 + 1];
                int qj = pos[row * 4 + 2];
                int ql = pos[row * 4 + 3];
                float* dst = qr + (size_t)row * Dm + h * HDm;
                #pragma unroll
                for (int nt = 0; nt < 3; nt++) {
                    float o1[2], o2[2];
                    #pragma unroll
                    for (int i = 0; i < 2; i++) {
                        int jdim = nt * 8 + 2 * tig + i;
                        float2 cs = (jdim < 8)  ? tab_s[qi * 8 + jdim]
                                  : (jdim < 16) ? tab_s[qj * 8 + jdim - 8]
                                                : tab_l[ql * 8 + jdim - 16];
                        float x1 = d[mt][nt][2 * rh + i];
                        float x2 = d[mt][nt + 3][2 * rh + i];
                        o1[i] = (x1 * cs.x - x2 * cs.y) * scale;
                        o2[i] = (x1 * cs.y + x2 * cs.x) * scale;
                    }
                    int dlo = nt * 8 + 2 * tig;
                    *(float2*)(dst + dlo)         = make_float2(o1[0], o1[1]);
                    *(float2*)(dst + dlo + HALFm) = make_float2(o2[0], o2[1]);
                }
            }
        }
        return;
    }

    // mode 1: kv epilogue into kvr rows [row][768].
    const bool isK = bn < Dm;
    const int cb = bn + wn * 48;

    #pragma unroll
    for (int mt = 0; mt < 2; mt++) {
        #pragma unroll
        for (int rh = 0; rh < 2; rh++) {
            int row = bm + wm * 32 + mt * 16 + gid + rh * 8;
            if (row >= M) continue;
            __nv_bfloat16* dst = kvr + (size_t)row * KVW + cb;
            if (isK) {
                int cell = row % total;
                int l = 0;
                #pragma unroll
                for (int q = 1; q < Lm; q++) if (cell >= sh_off[q]) l = q;
                int rem = cell - sh_off[l];
                int Wl = sh_Ws[l];
                int ic = rem / Wl;
                int jc = rem - ic * Wl;
                #pragma unroll
                for (int nt = 0; nt < 3; nt++) {
                    float o1[2], o2[2];
                    #pragma unroll
                    for (int i = 0; i < 2; i++) {
                        int jdim = nt * 8 + 2 * tig + i;
                        float2 cs = (jdim < 8)  ? tab_s[ic * 8 + jdim]
                                  : (jdim < 16) ? tab_s[jc * 8 + jdim - 8]
                                                : tab_l[l * 8 + jdim - 16];
                        float x1 = d[mt][nt][2 * rh + i];
                        float x2 = d[mt][nt + 3][2 * rh + i];
                        o1[i] = x1 * cs.x - x2 * cs.y;
                        o2[i] = x1 * cs.y + x2 * cs.x;
                    }
                    int dlo = nt * 8 + 2 * tig;
                    *(uint32_t*)(dst + dlo)         = pack_bf16x2(o1[0], o1[1]);
                    *(uint32_t*)(dst + dlo + HALFm) = pack_bf16x2(o2[0], o2[1]);
                }
            } else {
                #pragma unroll
                for (int nt = 0; nt < 6; nt++) {
                    int dd = nt * 8 + 2 * tig;
                    *(uint32_t*)(dst + dd) =
                        pack_bf16x2(d[mt][nt][2 * rh], d[mt][nt][2 * rh + 1]);
                }
            }
        }
    }
}

// ---------------------------------------------------------------------------
// out GEMM, split-K: blockIdx.z selects a K slice of 3 chunks (96 cols).
// Writes fp32 partials (no residual) to part + z*M*N.
// ---------------------------------------------------------------------------
__global__ void __launch_bounds__(256)
gemm_out_kernel(const float* __restrict__ A, const float* __restrict__ W,
                float* __restrict__ part, int M, int N, int K) {
    __shared__ uint2 As[2][128 * 12];
    __shared__ uint2 Bs[2][96 * 12];

    const int tid  = threadIdx.x;
    const int lane = tid & 31;
    const int warp = tid >> 5;
    const int wm   = warp >> 1;
    const int wn   = warp & 1;
    const int bm   = blockIdx.y * 128;
    const int bn   = blockIdx.x * 96;
    const int ksl  = blockIdx.z;              // 0..KSPLIT-1
    const int tig  = lane & 3;
    const int gid  = lane >> 2;

    float d[2][6][4];
    #pragma unroll
    for (int mt = 0; mt < 2; mt++)
        #pragma unroll
        for (int nt = 0; nt < 6; nt++)
            #pragma unroll
            for (int i = 0; i < 4; i++) d[mt][nt][i] = 0.f;

    const int nchunk = (K >> 5) / KSPLIT;     // 3
    const int kbase  = ksl * nchunk * 32;
    float4 pa[4], pb[3];

    #pragma unroll
    for (int i = 0; i < 4; i++) {
        int idx = tid + 256 * i;
        int row = idx >> 3, c4 = (idx & 7) << 2;
        int gr = bm + row;
        pa[i] = (gr < M) ? *(const float4*)(A + (size_t)gr * K + kbase + c4)
                         : make_float4(0.f, 0.f, 0.f, 0.f);
    }
    #pragma unroll
    for (int i = 0; i < 3; i++) {
        int idx = tid + 256 * i;
        int row = idx >> 3, c4 = (idx & 7) << 2;
        pb[i] = *(const float4*)(W + (size_t)(bn + row) * K + kbase + c4);
    }
    #pragma unroll
    for (int i = 0; i < 4; i++) {
        int idx = tid + 256 * i;
        store_tile_u2(As[0], idx >> 3, (idx & 7) << 2, pa[i]);
    }
    #pragma unroll
    for (int i = 0; i < 3; i++) {
        int idx = tid + 256 * i;
        store_tile_u2(Bs[0], idx >> 3, (idx & 7) << 2, pb[i]);
    }
    __syncthreads();

    for (int c = 0; c < nchunk; c++) {
        const int cur = c & 1;
        const bool more = (c + 1 < nchunk);

        if (more) {
            int k0 = kbase + (c + 1) * 32;
            #pragma unroll
            for (int i = 0; i < 4; i++) {
                int idx = tid + 256 * i;
                int row = idx >> 3, c4 = (idx & 7) << 2;
                int gr = bm + row;
                pa[i] = (gr < M) ? *(const float4*)(A + (size_t)gr * K + k0 + c4)
                                 : make_float4(0.f, 0.f, 0.f, 0.f);
            }
            #pragma unroll
            for (int i = 0; i < 3; i++) {
                int idx = tid + 256 * i;
                int row = idx >> 3, c4 = (idx & 7) << 2;
                pb[i] = *(const float4*)(W + (size_t)(bn + row) * K + k0 + c4);
            }
        }

        #pragma unroll
        for (int ks = 0; ks < 2; ks++) {
            uint2 ua[2][2];
            #pragma unroll
            for (int mt = 0; mt < 2; mt++) {
                int r = wm * 32 + mt * 16 + gid;
                ua[mt][0] = As[cur][r * 12 + ks * 4 + tig];
                ua[mt][1] = As[cur][(r + 8) * 12 + ks * 4 + tig];
            }
            uint2 ub[6];
            #pragma unroll
            for (int nt = 0; nt < 6; nt++) {
                int nn = wn * 48 + nt * 8 + gid;
                ub[nt] = Bs[cur][nn * 12 + ks * 4 + tig];
            }
            #pragma unroll
            for (int mt = 0; mt < 2; mt++)
                #pragma unroll
                for (int nt = 0; nt < 6; nt++)
                    asm volatile(
                        "mma.sync.aligned.m16n8k16.row.col.f32.bf16.bf16.f32 "
                        "{%0,%1,%2,%3}, {%4,%5,%6,%7}, {%8,%9}, {%0,%1,%2,%3};"
                        : "+f"(d[mt][nt][0]), "+f"(d[mt][nt][1]),
                          "+f"(d[mt][nt][2]), "+f"(d[mt][nt][3])
                        : "r"(ua[mt][0].x), "r"(ua[mt][1].x),
                          "r"(ua[mt][0].y), "r"(ua[mt][1].y),
                          "r"(ub[nt].x), "r"(ub[nt].y));
        }

        if (more) {
            #pragma unroll
            for (int i = 0; i < 4; i++) {
                int idx = tid + 256 * i;
                store_tile_u2(As[cur ^ 1], idx >> 3, (idx & 7) << 2, pa[i]);
            }
            #pragma unroll
            for (int i = 0; i < 3; i++) {
                int idx = tid + 256 * i;
                store_tile_u2(Bs[cur ^ 1], idx >> 3, (idx & 7) << 2, pb[i]);
            }
        }
        __syncthreads();
    }

    float* dstp = part + (size_t)ksl * M * N;
    #pragma unroll
    for (int mt = 0; mt < 2; mt++)
        #pragma unroll
        for (int rh = 0; rh < 2; rh++) {
            int row = bm + wm * 32 + mt * 16 + gid + rh * 8;
            if (row >= M) continue;
            #pragma unroll
            for (int nt = 0; nt < 6; nt++) {
                int col = bn + wn * 48 + nt * 8 + 2 * tig;
                *(float2*)(dstp + (size_t)row * N + col) =
                    make_float2(d[mt][nt][2 * rh], d[mt][nt][2 * rh + 1]);
            }
        }
}

// ---------------------------------------------------------------------------
// combine: out = sum of KSPLIT partials + residual  (fixed order, determinist)
// ---------------------------------------------------------------------------
__global__ void combine_kernel(const float* __restrict__ part,
                               const float* __restrict__ R,
                               float* __restrict__ C, int n4, int stride4) {
    int i = blockIdx.x * blockDim.x + threadIdx.x;
    if (i >= n4) return;
    const float4* p = (const float4*)part;
    float4 a = p[i];
    float4 b = p[i + stride4];
    float4 c = p[i + 2 * stride4];
    float4 e = p[i + 3 * stride4];
    float4 r = ((const float4*)R)[i];
    float4 o;
    o.x = a.x + b.x + c.x + e.x + r.x;
    o.y = a.y + b.y + c.y + e.y + r.y;
    o.z = a.z + b.z + c.z + e.z + r.z;
    o.w = a.w + b.w + c.w + e.w + r.w;
    ((float4*)C)[i] = o;
}

// ---------------------------------------------------------------------------
// Attention: one block per query, 8 warps (warp = head), bf16 K/V in kvr
// unified rows (K at h*48, V at 384+h*48 — 96B per head slice, no padding).
// ---------------------------------------------------------------------------
__global__ void __launch_bounds__(256)
attn_kernel(const float* __restrict__ qr,
            const int* __restrict__ pos,
            const int* __restrict__ shapes,
            const __nv_bfloat16* __restrict__ kvr,
            float* __restrict__ attn_out,
            int total, int Mkv) {
    __shared__ float sc_sh[NHm][NKEY];
    __shared__ int   rb_sh[NKEY];
    __shared__ int   ci_sh[Lm], cj_sh[Lm], Hs_sh[Lm], Ws_sh[Lm], offs_sh[Lm];

    const int n = blockIdx.x;
    const int t = threadIdx.x;

    if (t == 0) {
        int qi = pos[n * 4 + 1], qj = pos[n * 4 + 2], ql = pos[n * 4 + 3];
        float Hq = (float)shapes[2 * ql];
        float Wq = (float)shapes[2 * ql + 1];
        int off = 0;
        #pragma unroll
        for (int l = 0; l < Lm; l++) {
            int H = shapes[2 * l], W = shapes[2 * l + 1];
            Hs_sh[l] = H; Ws_sh[l] = W; offs_sh[l] = off; off += H * W;
            ci_sh[l] = (int)floorf(((float)qi + 0.5f) * (float)H / Hq);
            cj_sh[l] = (int)floorf(((float)qj + 0.5f) * (float)W / Wq);
        }
    }
    __syncthreads();

    const int bq = pos[n * 4 + 0];
    if (t < NKEY) {
        int l  = t / 49;
        int rr = t - l * 49;
        int si = rr / 7, sj = rr - (rr / 7) * 7;
        int H = Hs_sh[l], W = Ws_sh[l];
        int ii = ci_sh[l] + si - 3;
        int jj = cj_sh[l] + sj - 3;
        bool vld = (ii >= 0) && (ii < H) && (jj >= 0) && (jj < W);
        rb_sh[t] = vld ? (bq * total + offs_sh[l] + ii * W + jj) : -1;
    }
    __syncthreads();

    const int h    = t >> 5;
    const int lane = t & 31;
    const int part = lane & 7;
    const int ksub = lane >> 3;
    const bool act = (part < 6);

    const __nv_bfloat16* kbase = kvr + h * HDm;
    const __nv_bfloat16* vbase = kvr + Dm + h * HDm;

    float4 qa = make_float4(0.f, 0.f, 0.f, 0.f);
    float4 qb = make_float4(0.f, 0.f, 0.f, 0.f);
    if (act) {
        qa = *(const float4*)(qr + n * Dm + h * HDm + part * 8);
        qb = *(const float4*)(qr + n * Dm + h * HDm + part * 8 + 4);
    }

    // ---- score pass: 49 iterations (4 keys each), pipelined 7-deep ----
    for (int ob = 0; ob < 49; ob += 7) {
        uint4 kr[7];
        int   rbs[7];
        #pragma unroll
        for (int u = 0; u < 7; u++) {
            int key = (ob + u) * 4 + ksub;
            int rb  = rb_sh[key];
            rbs[u]  = rb;
            kr[u] = make_uint4(0u, 0u, 0u, 0u);
            if (act && rb >= 0)
                kr[u] = *(const uint4*)(kbase + (size_t)rb * KVW + part * 8);
        }
        #pragma unroll
        for (int u = 0; u < 7; u++) {
            float2 f0 = __bfloat1622float2(*(const __nv_bfloat162*)&kr[u].x);
            float2 f1 = __bfloat1622float2(*(const __nv_bfloat162*)&kr[u].y);
            float2 f2 = __bfloat1622float2(*(const __nv_bfloat162*)&kr[u].z);
            float2 f3 = __bfloat1622float2(*(const __nv_bfloat162*)&kr[u].w);
            float partial = qa.x * f0.x + qa.y * f0.y + qa.z * f1.x + qa.w * f1.y
                          + qb.x * f2.x + qb.y * f2.y + qb.z * f3.x + qb.w * f3.y;
            partial += __shfl_xor_sync(0xFFFFFFFFu, partial, 4);
            partial += __shfl_xor_sync(0xFFFFFFFFu, partial, 2);
            partial += __shfl_xor_sync(0xFFFFFFFFu, partial, 1);
            if (part == 0) {
                int key = (ob + u) * 4 + ksub;
                sc_sh[h][key] = (rbs[u] >= 0) ? partial : -1e30f;
            }
        }
    }
    __syncwarp();

    // ---- softmax over 196 keys (per warp) ----
    float m = -1e30f;
    for (int k = lane; k < NKEY; k += 32) m = fmaxf(m, sc_sh[h][k]);
    #pragma unroll
    for (int o = 16; o; o >>= 1) m = fmaxf(m, __shfl_xor_sync(0xFFFFFFFFu, m, o));
    float lsum = 0.f;
    for (int k = lane; k < NKEY; k += 32) {
        float pe = __expf(sc_sh[h][k] - m);
        sc_sh[h][k] = pe;
        lsum += pe;
    }
    #pragma unroll
    for (int o = 16; o; o >>= 1) lsum += __shfl_xor_sync(0xFFFFFFFFu, lsum, o);
    __syncwarp();

    // ---- V pass: 49 iterations (4 keys each), pipelined 7-deep ----
    float a0 = 0.f, a1 = 0.f, a2 = 0.f, a3 = 0.f;
    float a4 = 0.f, a5 = 0.f, a6 = 0.f, a7 = 0.f;
    for (int ob = 0; ob < 49; ob += 7) {
        uint4 vr[7];
        #pragma unroll
        for (int u = 0; u < 7; u++) {
            int key = (ob + u) * 4 + ksub;
            int rb  = rb_sh[key];
            vr[u] = make_uint4(0u, 0u, 0u, 0u);
            if (act && rb >= 0)
                vr[u] = *(const uint4*)(vbase + (size_t)rb * KVW + part * 8);
        }
        #pragma unroll
        for (int u = 0; u < 7; u++) {
            int key = (ob + u) * 4 + ksub;
            float pk = sc_sh[h][key];
            float2 f0 = __bfloat1622float2(*(const __nv_bfloat162*)&vr[u].x);
            float2 f1 = __bfloat1622float2(*(const __nv_bfloat162*)&vr[u].y);
            float2 f2 = __bfloat1622float2(*(const __nv_bfloat162*)&vr[u].z);
            float2 f3 = __bfloat1622float2(*(const __nv_bfloat162*)&vr[u].w);
            a0 += pk * f0.x; a1 += pk * f0.y;
            a2 += pk * f1.x; a3 += pk * f1.y;
            a4 += pk * f2.x; a5 += pk * f2.y;
            a6 += pk * f3.x; a7 += pk * f3.y;
        }
    }
    #pragma unroll
    for (int o = 16; o >= 8; o >>= 1) {
        a0 += __shfl_xor_sync(0xFFFFFFFFu, a0, o);
        a1 += __shfl_xor_sync(0xFFFFFFFFu, a1, o);
        a2 += __shfl_xor_sync(0xFFFFFFFFu, a2, o);
        a3 += __shfl_xor_sync(0xFFFFFFFFu, a3, o);
        a4 += __shfl_xor_sync(0xFFFFFFFFu, a4, o);
        a5 += __shfl_xor_sync(0xFFFFFFFFu, a5, o);
        a6 += __shfl_xor_sync(0xFFFFFFFFu, a6, o);
        a7 += __shfl_xor_sync(0xFFFFFFFFu, a7, o);
    }

    if (ksub == 0 && act) {
        float inv = 1.f / lsum;
        float* dst = attn_out + n * Dm + h * HDm + part * 8;
        *(float4*)dst       = make_float4(a0 * inv, a1 * inv, a2 * inv, a3 * inv);
        *(float4*)(dst + 4) = make_float4(a4 * inv, a5 * inv, a6 * inv, a7 * inv);
    }
}

// ---------------------------------------------------------------------------
// kernel_launch
// ---------------------------------------------------------------------------
extern "C" void kernel_launch(void* const* d_in, const int* in_sizes, int n_in,
                              void* d_out, int out_size) {
    const float* query  = (const float*)d_in[0];
    const int*   pos    = (const int*)d_in[1];
    const float* fm     = (const float*)d_in[3];
    const int*   shapes = (const int*)d_in[4];
    const float* nw     = (const float*)d_in[5];
    const float* nb     = (const float*)d_in[6];
    const float* w_q    = (const float*)d_in[7];
    const float* w_kv   = (const float*)d_in[8];
    const float* w_out  = (const float*)d_in[9];
    float* out = (float*)d_out;

    const int D  = Dm;
    const int NQ = in_sizes[0] / D;
    const int Bn = in_sizes[2] - 1;
    const int total = in_sizes[3] / (Bn * D);
    const int Mkv = Bn * total;

    float *qrp, *attn, *partp;
    __nv_bfloat16 *kvrp;
    float2 *tabs, *tabl;
    cudaGetSymbolAddress((void**)&qrp,   g_qr);
    cudaGetSymbolAddress((void**)&attn,  g_attn);
    cudaGetSymbolAddress((void**)&partp, g_part);
    cudaGetSymbolAddress((void**)&kvrp,  g_kvr);
    cudaGetSymbolAddress((void**)&tabs,  g_tab_s);
    cudaGetSymbolAddress((void**)&tabl,  g_tab_l);

    // 0. RoPE tables
    tab_kernel<<<3, 384>>>(tabs, tabl);

    // 1+2+3. Fused GEMM: kv projection (mode 1) + LN + q projection (mode 2).
    {
        const int kvTiles = (Mkv + 127) / 128;            // 170
        const int qTiles  = (NQ + 127) / 128;             // 8
        dim3 grid((2 * D) / 96, kvTiles + qTiles);        // 8 x 178
        gemm_fused_kernel<<<grid, 256>>>(fm, w_kv, query, w_q, nw, nb,
                                         qrp, kvrp, shapes, pos, tabs, tabl,
                                         Mkv, NQ, total, kvTiles);
    }

    // 4. sparse neighborhood attention
    attn_kernel<<<NQ, 256>>>(qrp, pos, shapes, kvrp, attn, total, Mkv);

    // 5. out = attn @ w_out^T + residual  (split-K=4 + combine)
    {
        dim3 grid(D / 96, (NQ + 127) / 128, KSPLIT);
        gemm_out_kernel<<<grid, 256>>>(attn, w_out, partp, NQ, D, D);
        int n4 = NQ * D / 4, stride4 = n4;
        combine_kernel<<<(n4 + 255) / 256, 256>>>(partp, query, out, n4, stride4);
    }
}

// round 17
// speedup vs baseline: 1.1356x; 1.1356x over previous
#include <cuda_runtime.h>
#include <cuda_bf16.h>
#include <cstdint>

// ---------------------------------------------------------------------------
// Constants fixed by the dataset:
//   N=1024 queries, B=4, D=384, NH=8, HD=48, HALF=24, NF=8, L=4, NS=7
//   total cells per batch = 5440, K(keys/query) = 196, Mkv = 21760
// ---------------------------------------------------------------------------
#define Dm 384
#define NHm 8
#define HDm 48
#define HALFm 24
#define Lm 4
#define NKEY 196
#define MAXQ 1024
#define MAXROWS 21760
#define KVW 768             // kvr row width (K 0..383 rotated, V 384..767)
#define KSPLIT 4            // out-GEMM split-K factor

// ---------------- device scratch (static; no cudaMalloc) -------------------
__device__ float g_xn[MAXQ * Dm];        // layernorm output
__device__ float g_qr[MAXQ * Dm];        // rotated+scaled q (fp32)
__device__ float g_attn[MAXQ * Dm];      // attention output
__device__ float g_part[KSPLIT * MAXQ * Dm];  // out-GEMM split-K partials
__device__ __align__(16) __nv_bfloat16 g_kvr[(size_t)MAXROWS * KVW];
__device__ float2 g_tab_s[128 * 8];      // cos/sin(pos * 10^(-f/8)), pos<128
__device__ float2 g_tab_l[4 * 8];        // cos/sin(lvl * 10^(+f/8))

// ---------------------------------------------------------------------------
__device__ __forceinline__ uint32_t pack_bf16x2(float lo, float hi) {
    uint32_t r;
    asm("cvt.rn.bf16x2.f32 %0, %1, %2;" : "=r"(r) : "f"(hi), "f"(lo));
    return r;
}

// ---------------------------------------------------------------------------
// LayerNorm (one block per query row, 384 threads) + RoPE table generation
// folded into blocks 0..2.  (Identical to R14 — do NOT tax the GEMM.)
// ---------------------------------------------------------------------------
__global__ void ln_kernel(const float* __restrict__ x,
                          const float* __restrict__ w,
                          const float* __restrict__ b,
                          float* __restrict__ y,
                          float2* __restrict__ tab_s,
                          float2* __restrict__ tab_l) {
    if (blockIdx.x < 3) {
        int t = blockIdx.x * 384 + threadIdx.x;
        if (t < 128 * 8) {
            int p = t >> 3, f = t & 7;
            float s, c;
            sincosf((float)p * exp10f(-(float)f * 0.125f), &s, &c);
            tab_s[t] = make_float2(c, s);
        } else if (t < 128 * 8 + 32) {
            int u = t - 1024;
            int l = u >> 3, f = u & 7;
            float s, c;
            sincosf((float)l * exp10f((float)f * 0.125f), &s, &c);
            tab_l[u] = make_float2(c, s);
        }
    }

    int n = blockIdx.x;
    int d = threadIdx.x;
    float v = x[n * Dm + d];
    float s = v, s2 = v * v;
    #pragma unroll
    for (int o = 16; o; o >>= 1) {
        s  += __shfl_xor_sync(0xFFFFFFFFu, s,  o);
        s2 += __shfl_xor_sync(0xFFFFFFFFu, s2, o);
    }
    __shared__ float sw[12], sw2[12];
    int wid = d >> 5, lane = d & 31;
    if (lane == 0) { sw[wid] = s; sw2[wid] = s2; }
    __syncthreads();
    if (d == 0) {
        float a = 0.f, a2 = 0.f;
        #pragma unroll
        for (int i = 0; i < 12; i++) { a += sw[i]; a2 += sw2[i]; }
        sw[0] = a; sw2[0] = a2;
    }
    __syncthreads();
    float mu  = sw[0] * (1.f / Dm);
    float var = sw2[0] * (1.f / Dm) - mu * mu;
    float r = rsqrtf(var + 1e-5f);
    y[n * Dm + d] = (v - mu) * r * w[d] + b[d];
}

// ---------------------------------------------------------------------------
// smem staging store: fp32 float4 -> interleaved bf16 pair layout
// ---------------------------------------------------------------------------
__device__ __forceinline__ void store_tile_u2(uint2* sm, int row, int c4, float4 v) {
    uint32_t lo = pack_bf16x2(v.x, v.y);
    uint32_t hi = pack_bf16x2(v.z, v.w);
    int P  = c4 >> 1;                 // even pair index in [0,16)
    int ks = P >> 3;
    int p0 = P & 7, p1 = (P + 1) & 7; // same ks (P even)
    uint32_t* base = (uint32_t*)(sm + row * 12 + ks * 4);
    base[((p0 & 3) << 1) | (p0 >> 2)] = lo;
    base[((p1 & 3) << 1) | (p1 >> 2)] = hi;
}

// ---------------------------------------------------------------------------
// Fused GEMM launch: kv projection (mode 1) + q projection (mode 2) in ONE
// grid (identical to R14). q tiles ride the kv tail wave.
// CTA tile 128x96, K=384, K-step 32, 8 warps 4(m)x2(n), double-buffered.
// ---------------------------------------------------------------------------
__global__ void __launch_bounds__(256)
gemm_fused_kernel(const float* __restrict__ fm, const float* __restrict__ wkv,
                  const float* __restrict__ xn, const float* __restrict__ wq,
                  float* __restrict__ qr, __nv_bfloat16* __restrict__ kvr,
                  const int* __restrict__ shapes, const int* __restrict__ pos,
                  const float2* __restrict__ tab_s, const float2* __restrict__ tab_l,
                  int Mkv, int NQ, int total, int kvTiles) {
    __shared__ uint2 As[2][128 * 12];
    __shared__ uint2 Bs[2][96 * 12];
    __shared__ int sh_Ws[Lm], sh_off[Lm];

    const int tid  = threadIdx.x;
    const int lane = tid & 31;
    const int warp = tid >> 5;
    const int wm   = warp >> 1;   // 0..3
    const int wn   = warp & 1;    // 0..1
    const int tig  = lane & 3;
    const int gid  = lane >> 2;

    int mode, bm, bn, M;
    const float *A, *W;
    if ((int)blockIdx.y < kvTiles) {
        mode = 1;
        bm = blockIdx.y * 128;
        bn = blockIdx.x * 96;
        A = fm; W = wkv; M = Mkv;
    } else {
        if (blockIdx.x >= 4) return;
        mode = 2;
        bm = (blockIdx.y - kvTiles) * 128;
        bn = blockIdx.x * 96;
        A = xn; W = wq; M = NQ;
    }
    const int K = Dm;

    if (mode == 1 && tid == 0) {
        int off = 0;
        #pragma unroll
        for (int l = 0; l < Lm; l++) {
            int H = shapes[2 * l], Wl = shapes[2 * l + 1];
            sh_Ws[l] = Wl; sh_off[l] = off; off += H * Wl;
        }
    }

    float d[2][6][4];
    #pragma unroll
    for (int mt = 0; mt < 2; mt++)
        #pragma unroll
        for (int nt = 0; nt < 6; nt++)
            #pragma unroll
            for (int i = 0; i < 4; i++) d[mt][nt][i] = 0.f;

    const int nchunk = K >> 5;
    float4 pa[4], pb[3];

    #pragma unroll
    for (int i = 0; i < 4; i++) {
        int idx = tid + 256 * i;
        int row = idx >> 3, c4 = (idx & 7) << 2;
        int gr = bm + row;
        pa[i] = (gr < M) ? *(const float4*)(A + (size_t)gr * K + c4)
                         : make_float4(0.f, 0.f, 0.f, 0.f);
    }
    #pragma unroll
    for (int i = 0; i < 3; i++) {
        int idx = tid + 256 * i;
        int row = idx >> 3, c4 = (idx & 7) << 2;
        pb[i] = *(const float4*)(W + (size_t)(bn + row) * K + c4);
    }
    #pragma unroll
    for (int i = 0; i < 4; i++) {
        int idx = tid + 256 * i;
        store_tile_u2(As[0], idx >> 3, (idx & 7) << 2, pa[i]);
    }
    #pragma unroll
    for (int i = 0; i < 3; i++) {
        int idx = tid + 256 * i;
        store_tile_u2(Bs[0], idx >> 3, (idx & 7) << 2, pb[i]);
    }
    __syncthreads();

    for (int c = 0; c < nchunk; c++) {
        const int cur = c & 1;
        const bool more = (c + 1 < nchunk);

        if (more) {
            int k0 = (c + 1) * 32;
            #pragma unroll
            for (int i = 0; i < 4; i++) {
                int idx = tid + 256 * i;
                int row = idx >> 3, c4 = (idx & 7) << 2;
                int gr = bm + row;
                pa[i] = (gr < M) ? *(const float4*)(A + (size_t)gr * K + k0 + c4)
                                 : make_float4(0.f, 0.f, 0.f, 0.f);
            }
            #pragma unroll
            for (int i = 0; i < 3; i++) {
                int idx = tid + 256 * i;
                int row = idx >> 3, c4 = (idx & 7) << 2;
                pb[i] = *(const float4*)(W + (size_t)(bn + row) * K + k0 + c4);
            }
        }

        #pragma unroll
        for (int ks = 0; ks < 2; ks++) {
            uint2 ua[2][2];
            #pragma unroll
            for (int mt = 0; mt < 2; mt++) {
                int r = wm * 32 + mt * 16 + gid;
                ua[mt][0] = As[cur][r * 12 + ks * 4 + tig];
                ua[mt][1] = As[cur][(r + 8) * 12 + ks * 4 + tig];
            }
            uint2 ub[6];
            #pragma unroll
            for (int nt = 0; nt < 6; nt++) {
                int nn = wn * 48 + nt * 8 + gid;
                ub[nt] = Bs[cur][nn * 12 + ks * 4 + tig];
            }
            #pragma unroll
            for (int mt = 0; mt < 2; mt++)
                #pragma unroll
                for (int nt = 0; nt < 6; nt++)
                    asm volatile(
                        "mma.sync.aligned.m16n8k16.row.col.f32.bf16.bf16.f32 "
                        "{%0,%1,%2,%3}, {%4,%5,%6,%7}, {%8,%9}, {%0,%1,%2,%3};"
                        : "+f"(d[mt][nt][0]), "+f"(d[mt][nt][1]),
                          "+f"(d[mt][nt][2]), "+f"(d[mt][nt][3])
                        : "r"(ua[mt][0].x), "r"(ua[mt][1].x),
                          "r"(ua[mt][0].y), "r"(ua[mt][1].y),
                          "r"(ub[nt].x), "r"(ub[nt].y));
        }

        if (more) {
            #pragma unroll
            for (int i = 0; i < 4; i++) {
                int idx = tid + 256 * i;
                store_tile_u2(As[cur ^ 1], idx >> 3, (idx & 7) << 2, pa[i]);
            }
            #pragma unroll
            for (int i = 0; i < 3; i++) {
                int idx = tid + 256 * i;
                store_tile_u2(Bs[cur ^ 1], idx >> 3, (idx & 7) << 2, pb[i]);
            }
        }
        __syncthreads();
    }

    if (mode == 2) {
        // q epilogue: rotate (nt, nt+3) pairs per query row, scale, fp32 out
        const int h = bn / HDm + wn;
        const float scale = 0.14433756729740643f;   // 1/sqrt(48)
        #pragma unroll
        for (int mt = 0; mt < 2; mt++) {
            #pragma unroll
            for (int rh = 0; rh < 2; rh++) {
                int row = bm + wm * 32 + mt * 16 + gid + rh * 8;
                if (row >= M) continue;
                int qi = pos[row * 4 + 1];
                int qj = pos[row * 4 + 2];
                int ql = pos[row * 4 + 3];
                float* dst = qr + (size_t)row * Dm + h * HDm;
                #pragma unroll
                for (int nt = 0; nt < 3; nt++) {
                    float o1[2], o2[2];
                    #pragma unroll
                    for (int i = 0; i < 2; i++) {
                        int jdim = nt * 8 + 2 * tig + i;
                        float2 cs = (jdim < 8)  ? tab_s[qi * 8 + jdim]
                                  : (jdim < 16) ? tab_s[qj * 8 + jdim - 8]
                                                : tab_l[ql * 8 + jdim - 16];
                        float x1 = d[mt][nt][2 * rh + i];
                        float x2 = d[mt][nt + 3][2 * rh + i];
                        o1[i] = (x1 * cs.x - x2 * cs.y) * scale;
                        o2[i] = (x1 * cs.y + x2 * cs.x) * scale;
                    }
                    int dlo = nt * 8 + 2 * tig;
                    *(float2*)(dst + dlo)         = make_float2(o1[0], o1[1]);
                    *(float2*)(dst + dlo + HALFm) = make_float2(o2[0], o2[1]);
                }
            }
        }
        return;
    }

    // mode 1: kv epilogue into kvr rows [row][768].
    const bool isK = bn < Dm;
    const int cb = bn + wn * 48;

    #pragma unroll
    for (int mt = 0; mt < 2; mt++) {
        #pragma unroll
        for (int rh = 0; rh < 2; rh++) {
            int row = bm + wm * 32 + mt * 16 + gid + rh * 8;
            if (row >= M) continue;
            __nv_bfloat16* dst = kvr + (size_t)row * KVW + cb;
            if (isK) {
                int cell = row % total;
                int l = 0;
                #pragma unroll
                for (int q = 1; q < Lm; q++) if (cell >= sh_off[q]) l = q;
                int rem = cell - sh_off[l];
                int Wl = sh_Ws[l];
                int ic = rem / Wl;
                int jc = rem - ic * Wl;
                #pragma unroll
                for (int nt = 0; nt < 3; nt++) {
                    float o1[2], o2[2];
                    #pragma unroll
                    for (int i = 0; i < 2; i++) {
                        int jdim = nt * 8 + 2 * tig + i;
                        float2 cs = (jdim < 8)  ? tab_s[ic * 8 + jdim]
                                  : (jdim < 16) ? tab_s[jc * 8 + jdim - 8]
                                                : tab_l[l * 8 + jdim - 16];
                        float x1 = d[mt][nt][2 * rh + i];
                        float x2 = d[mt][nt + 3][2 * rh + i];
                        o1[i] = x1 * cs.x - x2 * cs.y;
                        o2[i] = x1 * cs.y + x2 * cs.x;
                    }
                    int dlo = nt * 8 + 2 * tig;
                    *(uint32_t*)(dst + dlo)         = pack_bf16x2(o1[0], o1[1]);
                    *(uint32_t*)(dst + dlo + HALFm) = pack_bf16x2(o2[0], o2[1]);
                }
            } else {
                #pragma unroll
                for (int nt = 0; nt < 6; nt++) {
                    int dd = nt * 8 + 2 * tig;
                    *(uint32_t*)(dst + dd) =
                        pack_bf16x2(d[mt][nt][2 * rh], d[mt][nt][2 * rh + 1]);
                }
            }
        }
    }
}

// ---------------------------------------------------------------------------
// out GEMM, split-K: blockIdx.z selects a K slice of 3 chunks (96 cols).
// Writes fp32 partials to part + z*M*N.  (Validated in R15: 19.2 -> 8.3 us.)
// ---------------------------------------------------------------------------
__global__ void __launch_bounds__(256)
gemm_out_kernel(const float* __restrict__ A, const float* __restrict__ W,
                float* __restrict__ part, int M, int N, int K) {
    __shared__ uint2 As[2][128 * 12];
    __shared__ uint2 Bs[2][96 * 12];

    const int tid  = threadIdx.x;
    const int lane = tid & 31;
    const int warp = tid >> 5;
    const int wm   = warp >> 1;
    const int wn   = warp & 1;
    const int bm   = blockIdx.y * 128;
    const int bn   = blockIdx.x * 96;
    const int ksl  = blockIdx.z;              // 0..KSPLIT-1
    const int tig  = lane & 3;
    const int gid  = lane >> 2;

    float d[2][6][4];
    #pragma unroll
    for (int mt = 0; mt < 2; mt++)
        #pragma unroll
        for (int nt = 0; nt < 6; nt++)
            #pragma unroll
            for (int i = 0; i < 4; i++) d[mt][nt][i] = 0.f;

    const int nchunk = (K >> 5) / KSPLIT;     // 3
    const int kbase  = ksl * nchunk * 32;
    float4 pa[4], pb[3];

    #pragma unroll
    for (int i = 0; i < 4; i++) {
        int idx = tid + 256 * i;
        int row = idx >> 3, c4 = (idx & 7) << 2;
        int gr = bm + row;
        pa[i] = (gr < M) ? *(const float4*)(A + (size_t)gr * K + kbase + c4)
                         : make_float4(0.f, 0.f, 0.f, 0.f);
    }
    #pragma unroll
    for (int i = 0; i < 3; i++) {
        int idx = tid + 256 * i;
        int row = idx >> 3, c4 = (idx & 7) << 2;
        pb[i] = *(const float4*)(W + (size_t)(bn + row) * K + kbase + c4);
    }
    #pragma unroll
    for (int i = 0; i < 4; i++) {
        int idx = tid + 256 * i;
        store_tile_u2(As[0], idx >> 3, (idx & 7) << 2, pa[i]);
    }
    #pragma unroll
    for (int i = 0; i < 3; i++) {
        int idx = tid + 256 * i;
        store_tile_u2(Bs[0], idx >> 3, (idx & 7) << 2, pb[i]);
    }
    __syncthreads();

    for (int c = 0; c < nchunk; c++) {
        const int cur = c & 1;
        const bool more = (c + 1 < nchunk);

        if (more) {
            int k0 = kbase + (c + 1) * 32;
            #pragma unroll
            for (int i = 0; i < 4; i++) {
                int idx = tid + 256 * i;
                int row = idx >> 3, c4 = (idx & 7) << 2;
                int gr = bm + row;
                pa[i] = (gr < M) ? *(const float4*)(A + (size_t)gr * K + k0 + c4)
                                 : make_float4(0.f, 0.f, 0.f, 0.f);
            }
            #pragma unroll
            for (int i = 0; i < 3; i++) {
                int idx = tid + 256 * i;
                int row = idx >> 3, c4 = (idx & 7) << 2;
                pb[i] = *(const float4*)(W + (size_t)(bn + row) * K + k0 + c4);
            }
        }

        #pragma unroll
        for (int ks = 0; ks < 2; ks++) {
            uint2 ua[2][2];
            #pragma unroll
            for (int mt = 0; mt < 2; mt++) {
                int r = wm * 32 + mt * 16 + gid;
                ua[mt][0] = As[cur][r * 12 + ks * 4 + tig];
                ua[mt][1] = As[cur][(r + 8) * 12 + ks * 4 + tig];
            }
            uint2 ub[6];
            #pragma unroll
            for (int nt = 0; nt < 6; nt++) {
                int nn = wn * 48 + nt * 8 + gid;
                ub[nt] = Bs[cur][nn * 12 + ks * 4 + tig];
            }
            #pragma unroll
            for (int mt = 0; mt < 2; mt++)
                #pragma unroll
                for (int nt = 0; nt < 6; nt++)
                    asm volatile(
                        "mma.sync.aligned.m16n8k16.row.col.f32.bf16.bf16.f32 "
                        "{%0,%1,%2,%3}, {%4,%5,%6,%7}, {%8,%9}, {%0,%1,%2,%3};"
                        : "+f"(d[mt][nt][0]), "+f"(d[mt][nt][1]),
                          "+f"(d[mt][nt][2]), "+f"(d[mt][nt][3])
                        : "r"(ua[mt][0].x), "r"(ua[mt][1].x),
                          "r"(ua[mt][0].y), "r"(ua[mt][1].y),
                          "r"(ub[nt].x), "r"(ub[nt].y));
        }

        if (more) {
            #pragma unroll
            for (int i = 0; i < 4; i++) {
                int idx = tid + 256 * i;
                store_tile_u2(As[cur ^ 1], idx >> 3, (idx & 7) << 2, pa[i]);
            }
            #pragma unroll
            for (int i = 0; i < 3; i++) {
                int idx = tid + 256 * i;
                store_tile_u2(Bs[cur ^ 1], idx >> 3, (idx & 7) << 2, pb[i]);
            }
        }
        __syncthreads();
    }

    float* dstp = part + (size_t)ksl * M * N;
    #pragma unroll
    for (int mt = 0; mt < 2; mt++)
        #pragma unroll
        for (int rh = 0; rh < 2; rh++) {
            int row = bm + wm * 32 + mt * 16 + gid + rh * 8;
            if (row >= M) continue;
            #pragma unroll
            for (int nt = 0; nt < 6; nt++) {
                int col = bn + wn * 48 + nt * 8 + 2 * tig;
                *(float2*)(dstp + (size_t)row * N + col) =
                    make_float2(d[mt][nt][2 * rh], d[mt][nt][2 * rh + 1]);
            }
        }
}

// ---------------------------------------------------------------------------
// combine: out = sum of KSPLIT partials + residual (fixed order, determinist)
// ---------------------------------------------------------------------------
__global__ void combine_kernel(const float* __restrict__ part,
                               const float* __restrict__ R,
                               float* __restrict__ C, int n4, int stride4) {
    int i = blockIdx.x * blockDim.x + threadIdx.x;
    if (i >= n4) return;
    const float4* p = (const float4*)part;
    float4 a = p[i];
    float4 b = p[i + stride4];
    float4 c = p[i + 2 * stride4];
    float4 e = p[i + 3 * stride4];
    float4 r = ((const float4*)R)[i];
    float4 o;
    o.x = a.x + b.x + c.x + e.x + r.x;
    o.y = a.y + b.y + c.y + e.y + r.y;
    o.z = a.z + b.z + c.z + e.z + r.z;
    o.w = a.w + b.w + c.w + e.w + r.w;
    ((float4*)C)[i] = o;
}

// ---------------------------------------------------------------------------
// Attention: one block per query, 8 warps (warp = head), bf16 K/V in kvr
// unified rows (K at h*48, V at 384+h*48 — 96B per head slice, no padding).
// ---------------------------------------------------------------------------
__global__ void __launch_bounds__(256)
attn_kernel(const float* __restrict__ qr,
            const int* __restrict__ pos,
            const int* __restrict__ shapes,
            const __nv_bfloat16* __restrict__ kvr,
            float* __restrict__ attn_out,
            int total, int Mkv) {
    __shared__ float sc_sh[NHm][NKEY];
    __shared__ int   rb_sh[NKEY];
    __shared__ int   ci_sh[Lm], cj_sh[Lm], Hs_sh[Lm], Ws_sh[Lm], offs_sh[Lm];

    const int n = blockIdx.x;
    const int t = threadIdx.x;

    if (t == 0) {
        int qi = pos[n * 4 + 1], qj = pos[n * 4 + 2], ql = pos[n * 4 + 3];
        float Hq = (float)shapes[2 * ql];
        float Wq = (float)shapes[2 * ql + 1];
        int off = 0;
        #pragma unroll
        for (int l = 0; l < Lm; l++) {
            int H = shapes[2 * l], W = shapes[2 * l + 1];
            Hs_sh[l] = H; Ws_sh[l] = W; offs_sh[l] = off; off += H * W;
            ci_sh[l] = (int)floorf(((float)qi + 0.5f) * (float)H / Hq);
            cj_sh[l] = (int)floorf(((float)qj + 0.5f) * (float)W / Wq);
        }
    }
    __syncthreads();

    const int bq = pos[n * 4 + 0];
    if (t < NKEY) {
        int l  = t / 49;
        int rr = t - l * 49;
        int si = rr / 7, sj = rr - (rr / 7) * 7;
        int H = Hs_sh[l], W = Ws_sh[l];
        int ii = ci_sh[l] + si - 3;
        int jj = cj_sh[l] + sj - 3;
        bool vld = (ii >= 0) && (ii < H) && (jj >= 0) && (jj < W);
        rb_sh[t] = vld ? (bq * total + offs_sh[l] + ii * W + jj) : -1;
    }
    __syncthreads();

    const int h    = t >> 5;
    const int lane = t & 31;
    const int part = lane & 7;
    const int ksub = lane >> 3;
    const bool act = (part < 6);

    const __nv_bfloat16* kbase = kvr + h * HDm;
    const __nv_bfloat16* vbase = kvr + Dm + h * HDm;

    float4 qa = make_float4(0.f, 0.f, 0.f, 0.f);
    float4 qb = make_float4(0.f, 0.f, 0.f, 0.f);
    if (act) {
        qa = *(const float4*)(qr + n * Dm + h * HDm + part * 8);
        qb = *(const float4*)(qr + n * Dm + h * HDm + part * 8 + 4);
    }

    // ---- score pass: 49 iterations (4 keys each), pipelined 7-deep ----
    for (int ob = 0; ob < 49; ob += 7) {
        uint4 kr[7];
        int   rbs[7];
        #pragma unroll
        for (int u = 0; u < 7; u++) {
            int key = (ob + u) * 4 + ksub;
            int rb  = rb_sh[key];
            rbs[u]  = rb;
            kr[u] = make_uint4(0u, 0u, 0u, 0u);
            if (act && rb >= 0)
                kr[u] = *(const uint4*)(kbase + (size_t)rb * KVW + part * 8);
        }
        #pragma unroll
        for (int u = 0; u < 7; u++) {
            float2 f0 = __bfloat1622float2(*(const __nv_bfloat162*)&kr[u].x);
            float2 f1 = __bfloat1622float2(*(const __nv_bfloat162*)&kr[u].y);
            float2 f2 = __bfloat1622float2(*(const __nv_bfloat162*)&kr[u].z);
            float2 f3 = __bfloat1622float2(*(const __nv_bfloat162*)&kr[u].w);
            float partial = qa.x * f0.x + qa.y * f0.y + qa.z * f1.x + qa.w * f1.y
                          + qb.x * f2.x + qb.y * f2.y + qb.z * f3.x + qb.w * f3.y;
            partial += __shfl_xor_sync(0xFFFFFFFFu, partial, 4);
            partial += __shfl_xor_sync(0xFFFFFFFFu, partial, 2);
            partial += __shfl_xor_sync(0xFFFFFFFFu, partial, 1);
            if (part == 0) {
                int key = (ob + u) * 4 + ksub;
                sc_sh[h][key] = (rbs[u] >= 0) ? partial : -1e30f;
            }
        }
    }
    __syncwarp();

    // ---- softmax over 196 keys (per warp) ----
    float m = -1e30f;
    for (int k = lane; k < NKEY; k += 32) m = fmaxf(m, sc_sh[h][k]);
    #pragma unroll
    for (int o = 16; o; o >>= 1) m = fmaxf(m, __shfl_xor_sync(0xFFFFFFFFu, m, o));
    float lsum = 0.f;
    for (int k = lane; k < NKEY; k += 32) {
        float pe = __expf(sc_sh[h][k] - m);
        sc_sh[h][k] = pe;
        lsum += pe;
    }
    #pragma unroll
    for (int o = 16; o; o >>= 1) lsum += __shfl_xor_sync(0xFFFFFFFFu, lsum, o);
    __syncwarp();

    // ---- V pass: 49 iterations (4 keys each), pipelined 7-deep ----
    float a0 = 0.f, a1 = 0.f, a2 = 0.f, a3 = 0.f;
    float a4 = 0.f, a5 = 0.f, a6 = 0.f, a7 = 0.f;
    for (int ob = 0; ob < 49; ob += 7) {
        uint4 vr[7];
        #pragma unroll
        for (int u = 0; u < 7; u++) {
            int key = (ob + u) * 4 + ksub;
            int rb  = rb_sh[key];
            vr[u] = make_uint4(0u, 0u, 0u, 0u);
            if (act && rb >= 0)
                vr[u] = *(const uint4*)(vbase + (size_t)rb * KVW + part * 8);
        }
        #pragma unroll
        for (int u = 0; u < 7; u++) {
            int key = (ob + u) * 4 + ksub;
            float pk = sc_sh[h][key];
            float2 f0 = __bfloat1622float2(*(const __nv_bfloat162*)&vr[u].x);
            float2 f1 = __bfloat1622float2(*(const __nv_bfloat162*)&vr[u].y);
            float2 f2 = __bfloat1622float2(*(const __nv_bfloat162*)&vr[u].z);
            float2 f3 = __bfloat1622float2(*(const __nv_bfloat162*)&vr[u].w);
            a0 += pk * f0.x; a1 += pk * f0.y;
            a2 += pk * f1.x; a3 += pk * f1.y;
            a4 += pk * f2.x; a5 += pk * f2.y;
            a6 += pk * f3.x; a7 += pk * f3.y;
        }
    }
    #pragma unroll
    for (int o = 16; o >= 8; o >>= 1) {
        a0 += __shfl_xor_sync(0xFFFFFFFFu, a0, o);
        a1 += __shfl_xor_sync(0xFFFFFFFFu, a1, o);
        a2 += __shfl_xor_sync(0xFFFFFFFFu, a2, o);
        a3 += __shfl_xor_sync(0xFFFFFFFFu, a3, o);
        a4 += __shfl_xor_sync(0xFFFFFFFFu, a4, o);
        a5 += __shfl_xor_sync(0xFFFFFFFFu, a5, o);
        a6 += __shfl_xor_sync(0xFFFFFFFFu, a6, o);
        a7 += __shfl_xor_sync(0xFFFFFFFFu, a7, o);
    }

    if (ksub == 0 && act) {
        float inv = 1.f / lsum;
        float* dst = attn_out + n * Dm + h * HDm + part * 8;
        *(float4*)dst       = make_float4(a0 * inv, a1 * inv, a2 * inv, a3 * inv);
        *(float4*)(dst + 4) = make_float4(a4 * inv, a5 * inv, a6 * inv, a7 * inv);
    }
}

// ---------------------------------------------------------------------------
// kernel_launch
// ---------------------------------------------------------------------------
extern "C" void kernel_launch(void* const* d_in, const int* in_sizes, int n_in,
                              void* d_out, int out_size) {
    const float* query  = (const float*)d_in[0];
    const int*   pos    = (const int*)d_in[1];
    const float* fm     = (const float*)d_in[3];
    const int*   shapes = (const int*)d_in[4];
    const float* nw     = (const float*)d_in[5];
    const float* nb     = (const float*)d_in[6];
    const float* w_q    = (const float*)d_in[7];
    const float* w_kv   = (const float*)d_in[8];
    const float* w_out  = (const float*)d_in[9];
    float* out = (float*)d_out;

    const int D  = Dm;
    const int NQ = in_sizes[0] / D;
    const int Bn = in_sizes[2] - 1;
    const int total = in_sizes[3] / (Bn * D);
    const int Mkv = Bn * total;

    float *xn, *qrp, *attn, *partp;
    __nv_bfloat16 *kvrp;
    float2 *tabs, *tabl;
    cudaGetSymbolAddress((void**)&xn,    g_xn);
    cudaGetSymbolAddress((void**)&qrp,   g_qr);
    cudaGetSymbolAddress((void**)&attn,  g_attn);
    cudaGetSymbolAddress((void**)&partp, g_part);
    cudaGetSymbolAddress((void**)&kvrp,  g_kvr);
    cudaGetSymbolAddress((void**)&tabs,  g_tab_s);
    cudaGetSymbolAddress((void**)&tabl,  g_tab_l);

    // 1. LayerNorm (+ RoPE table generation in blocks 0..2)
    ln_kernel<<<NQ, Dm>>>(query, nw, nb, xn, tabs, tabl);

    // 2+3. Fused GEMM: kv projection (mode 1) + q projection (mode 2).
    {
        const int kvTiles = (Mkv + 127) / 128;            // 170
        const int qTiles  = (NQ + 127) / 128;             // 8
        dim3 grid((2 * D) / 96, kvTiles + qTiles);        // 8 x 178
        gemm_fused_kernel<<<grid, 256>>>(fm, w_kv, xn, w_q, qrp, kvrp,
                                         shapes, pos, tabs, tabl,
                                         Mkv, NQ, total, kvTiles);
    }

    // 4. sparse neighborhood attention (96B head slices, no padding)
    attn_kernel<<<NQ, 256>>>(qrp, pos, shapes, kvrp, attn, total, Mkv);

    // 5. out = attn @ w_out^T + residual  (split-K=4 + combine)
    {
        dim3 grid(D / 96, (NQ + 127) / 128, KSPLIT);
        gemm_out_kernel<<<grid, 256>>>(attn, w_out, partp, NQ, D, D);
        int n4 = NQ * D / 4, stride4 = n4;
        combine_kernel<<<(n4 + 255) / 256, 256>>>(partp, query, out, n4, stride4);
    }
}